// round 3
// baseline (speedup 1.0000x reference)
#include <cuda_runtime.h>
#include <cstdint>

// PRALoss single-pass reduction.
// Inputs: D_est [32,1,1024,1024] fp32, D_gt same. Output: scalar fp32.
//
// Per pixel (h,w):
//   s_est = sum_b est, s_gt = sum_b gt  -> mask = (s_est > s_gt)
//   sq_est = sum_b est^2, sq_diff = sum_b (est-gt)^2
// Global: diff2 = sum sq_diff ; G2 = sum sq_est ; H2 = sum sq_est*mask
// out = diff2/G2 + 0.1 * diff2/H2
//
// Stage 1: 1024 blocks x 256 threads; each thread owns one float4 pixel
//          group and loops over the 32 batch planes (coalesced, stride
//          4 MiB). Block partials -> __device__ scratch (deterministic,
//          no atomics, no init kernel).
// Stage 2: single block reduces 1024 partials in fp64, writes scalar.

#define BATCH 32
#define PLANE_F4 (1024 * 1024 / 4)   // float4 elements per [H,W] plane
#define THREADS 256
#define NBLOCKS (PLANE_F4 / THREADS) // 1024

__device__ float g_part[3][NBLOCKS]; // [0]=diff2, [1]=G2, [2]=H2 per block

__global__ __launch_bounds__(THREADS) void pra_main(const float4* __restrict__ est,
                                                    const float4* __restrict__ gt) {
    const int idx = blockIdx.x * THREADS + threadIdx.x;   // one float4-pixel group

    float4 s_est = make_float4(0.f, 0.f, 0.f, 0.f);
    float4 s_gt  = make_float4(0.f, 0.f, 0.f, 0.f);
    float4 sqe   = make_float4(0.f, 0.f, 0.f, 0.f);
    float4 sqd   = make_float4(0.f, 0.f, 0.f, 0.f);

#pragma unroll 4
    for (int b = 0; b < BATCH; b++) {
        const float4 e = est[idx + (size_t)b * PLANE_F4];
        const float4 g = gt [idx + (size_t)b * PLANE_F4];
        s_est.x += e.x; s_est.y += e.y; s_est.z += e.z; s_est.w += e.w;
        s_gt.x  += g.x; s_gt.y  += g.y; s_gt.z  += g.z; s_gt.w  += g.w;
        sqe.x = fmaf(e.x, e.x, sqe.x);
        sqe.y = fmaf(e.y, e.y, sqe.y);
        sqe.z = fmaf(e.z, e.z, sqe.z);
        sqe.w = fmaf(e.w, e.w, sqe.w);
        float dx = e.x - g.x, dy = e.y - g.y, dz = e.z - g.z, dw = e.w - g.w;
        sqd.x = fmaf(dx, dx, sqd.x);
        sqd.y = fmaf(dy, dy, sqd.y);
        sqd.z = fmaf(dz, dz, sqd.z);
        sqd.w = fmaf(dw, dw, sqd.w);
    }

    // per-thread scalars; mask applied per pixel from batch sums
    float d2 = (sqd.x + sqd.y) + (sqd.z + sqd.w);
    float g2 = (sqe.x + sqe.y) + (sqe.z + sqe.w);
    float h2 = (s_est.x > s_gt.x ? sqe.x : 0.f)
             + (s_est.y > s_gt.y ? sqe.y : 0.f)
             + (s_est.z > s_gt.z ? sqe.z : 0.f)
             + (s_est.w > s_gt.w ? sqe.w : 0.f);

    // warp reduce
#pragma unroll
    for (int off = 16; off > 0; off >>= 1) {
        d2 += __shfl_down_sync(0xFFFFFFFFu, d2, off);
        g2 += __shfl_down_sync(0xFFFFFFFFu, g2, off);
        h2 += __shfl_down_sync(0xFFFFFFFFu, h2, off);
    }

    __shared__ float s_d2[THREADS / 32], s_g2[THREADS / 32], s_h2[THREADS / 32];
    const int lane = threadIdx.x & 31;
    const int wid  = threadIdx.x >> 5;
    if (lane == 0) { s_d2[wid] = d2; s_g2[wid] = g2; s_h2[wid] = h2; }
    __syncthreads();

    if (wid == 0) {
        d2 = (lane < THREADS / 32) ? s_d2[lane] : 0.f;
        g2 = (lane < THREADS / 32) ? s_g2[lane] : 0.f;
        h2 = (lane < THREADS / 32) ? s_h2[lane] : 0.f;
#pragma unroll
        for (int off = 4; off > 0; off >>= 1) {
            d2 += __shfl_down_sync(0xFFFFFFFFu, d2, off);
            g2 += __shfl_down_sync(0xFFFFFFFFu, g2, off);
            h2 += __shfl_down_sync(0xFFFFFFFFu, h2, off);
        }
        if (lane == 0) {
            g_part[0][blockIdx.x] = d2;
            g_part[1][blockIdx.x] = g2;
            g_part[2][blockIdx.x] = h2;
        }
    }
}

__global__ __launch_bounds__(THREADS) void pra_finalize(float* __restrict__ out) {
    const int t = threadIdx.x;
    double d2 = 0.0, g2 = 0.0, h2 = 0.0;
#pragma unroll
    for (int i = t; i < NBLOCKS; i += THREADS) {
        d2 += (double)g_part[0][i];
        g2 += (double)g_part[1][i];
        h2 += (double)g_part[2][i];
    }

    // warp reduce in fp64
#pragma unroll
    for (int off = 16; off > 0; off >>= 1) {
        d2 += __shfl_down_sync(0xFFFFFFFFu, d2, off);
        g2 += __shfl_down_sync(0xFFFFFFFFu, g2, off);
        h2 += __shfl_down_sync(0xFFFFFFFFu, h2, off);
    }

    __shared__ double s_d2[THREADS / 32], s_g2[THREADS / 32], s_h2[THREADS / 32];
    const int lane = t & 31;
    const int wid  = t >> 5;
    if (lane == 0) { s_d2[wid] = d2; s_g2[wid] = g2; s_h2[wid] = h2; }
    __syncthreads();

    if (t == 0) {
#pragma unroll
        for (int w = 1; w < THREADS / 32; w++) {
            s_d2[0] += s_d2[w]; s_g2[0] += s_g2[w]; s_h2[0] += s_h2[w];
        }
        const double D2 = s_d2[0], G2 = s_g2[0], H2 = s_h2[0];
        out[0] = (float)(D2 / G2 + 0.1 * (D2 / H2));
    }
}

extern "C" void kernel_launch(void* const* d_in, const int* in_sizes, int n_in,
                              void* d_out, int out_size) {
    const float4* est = (const float4*)d_in[0];
    const float4* gt  = (const float4*)d_in[1];
    float* out = (float*)d_out;

    pra_main<<<NBLOCKS, THREADS>>>(est, gt);
    pra_finalize<<<1, THREADS>>>(out);
}